// round 1
// baseline (speedup 1.0000x reference)
#include <cuda_runtime.h>

// fullConv4d: x[2][16][24][24][24][24] (*) w[16][16][3][3][3][3] + b, SAME pad, stride 1.
// Strategy: smem-tiled direct conv, register-blocked 4co x 4t per thread. FMA-bound.

#define S      24
#define NCI    16
#define NCO    16
#define TILE   4
#define HALO   6          // TILE + 2
#define NT     (S / TILE) // 6
#define HALO4  (HALO*HALO*HALO*HALO)   // 1296

#define ST_T 1
#define ST_D 24
#define ST_W 576
#define ST_H 13824
#define ST_C 331776
#define ST_B (16 * 331776)

#define WS_FLOATS (NCI * 81 * NCO)     // 20736
#define XS_FLOATS (NCI * HALO4)        // 20736
#define SMEM_BYTES ((WS_FLOATS + XS_FLOATS) * (int)sizeof(float))  // 165888

__global__ __launch_bounds__(256, 1)
void conv4d_tiled_kernel(const float* __restrict__ x,
                         const float* __restrict__ wgt,
                         const float* __restrict__ bias,
                         float* __restrict__ out) {
    extern __shared__ float smem[];
    float* ws = smem;               // [ci][tap(81)][co]  (co contiguous)
    float* xs = smem + WS_FLOATS;   // [ci][6][6][6][6]

    const int tid = threadIdx.x;

    // ---- Load weights, transposed so co is the fastest dim ----
    // wgt layout: [co][ci][81]  ->  ws[(ci*81 + tap)*16 + co]
    for (int i = tid; i < NCO * NCI * 81; i += 256) {
        int co = i / (NCI * 81);
        int r  = i - co * (NCI * 81);      // r = ci*81 + tap
        ws[r * 16 + co] = wgt[i];
    }

    // ---- Decode block -> (b, tile origin) ----
    int bid = blockIdx.x;
    const int tT = bid % NT; bid /= NT;
    const int tD = bid % NT; bid /= NT;
    const int tW = bid % NT; bid /= NT;
    const int tH = bid % NT; bid /= NT;
    const int b  = bid;

    const int oh0 = tH * TILE, ow0 = tW * TILE, od0 = tD * TILE, ot0 = tT * TILE;

    // ---- Load halo'd input tile (zero padding at borders) ----
    const float* xb = x + (size_t)b * ST_B;
    for (int i = tid; i < NCI * HALO4; i += 256) {
        int it = i % HALO; int r = i / HALO;
        int id = r % HALO; r /= HALO;
        int iw = r % HALO; r /= HALO;
        int ih = r % HALO; int ci = r / HALO;
        int gh = oh0 + ih - 1, gw = ow0 + iw - 1;
        int gd = od0 + id - 1, gt = ot0 + it - 1;
        float v = 0.0f;
        if ((unsigned)gh < (unsigned)S && (unsigned)gw < (unsigned)S &&
            (unsigned)gd < (unsigned)S && (unsigned)gt < (unsigned)S)
            v = xb[ci * ST_C + gh * ST_H + gw * ST_W + gd * ST_D + gt];
        xs[i] = v;
    }
    __syncthreads();

    // ---- Thread -> (co-group of 4, position h,w,d; 4 t-positions) ----
    const int co4 = tid >> 6;        // 0..3
    const int p   = tid & 63;
    const int dd  = p & 3;
    const int w4  = (p >> 2) & 3;
    const int hh  = p >> 4;

    float acc[4][4];
    #pragma unroll
    for (int c = 0; c < 4; ++c)
        #pragma unroll
        for (int t = 0; t < 4; ++t) acc[c][t] = 0.0f;

    for (int ci = 0; ci < NCI; ++ci) {
        const float* xci = xs + ci * HALO4;
        const float* wci = ws + ci * (81 * 16);
        for (int kh = 0; kh < 3; ++kh) {
            for (int kw = 0; kw < 3; ++kw) {
                #pragma unroll
                for (int kd = 0; kd < 3; ++kd) {
                    const float* xr = xci + (hh + kh) * 216 + (w4 + kw) * 36 + (dd + kd) * 6;
                    float xv[6];
                    #pragma unroll
                    for (int j = 0; j < 6; ++j) xv[j] = xr[j];
                    const int tap0 = ((kh * 3 + kw) * 3 + kd) * 3;
                    #pragma unroll
                    for (int kt = 0; kt < 3; ++kt) {
                        const float4 wv = *reinterpret_cast<const float4*>(
                            wci + (tap0 + kt) * 16 + co4 * 4);
                        #pragma unroll
                        for (int t = 0; t < 4; ++t) {
                            const float xvv = xv[t + kt];
                            acc[0][t] = fmaf(wv.x, xvv, acc[0][t]);
                            acc[1][t] = fmaf(wv.y, xvv, acc[1][t]);
                            acc[2][t] = fmaf(wv.z, xvv, acc[2][t]);
                            acc[3][t] = fmaf(wv.w, xvv, acc[3][t]);
                        }
                    }
                }
            }
        }
    }

    // ---- Epilogue: add bias, vectorized store (ot0 is 16B aligned) ----
    float* ob = out + (size_t)b * ST_B + (oh0 + hh) * ST_H + (ow0 + w4) * ST_W
                + (od0 + dd) * ST_D + ot0;
    #pragma unroll
    for (int c = 0; c < 4; ++c) {
        const int co = co4 * 4 + c;
        const float bv = bias[co];
        float4 r;
        r.x = acc[c][0] + bv;
        r.y = acc[c][1] + bv;
        r.z = acc[c][2] + bv;
        r.w = acc[c][3] + bv;
        *reinterpret_cast<float4*>(ob + co * ST_C) = r;
    }
}

extern "C" void kernel_launch(void* const* d_in, const int* in_sizes, int n_in,
                              void* d_out, int out_size) {
    const float* x   = (const float*)d_in[0];
    const float* w   = (const float*)d_in[1];
    const float* bia = (const float*)d_in[2];
    float* out       = (float*)d_out;

    cudaFuncSetAttribute(conv4d_tiled_kernel,
                         cudaFuncAttributeMaxDynamicSharedMemorySize, SMEM_BYTES);

    const int grid = 2 * NT * NT * NT * NT;  // 2592
    conv4d_tiled_kernel<<<grid, 256, SMEM_BYTES>>>(x, w, bia, out);
}

// round 2
// speedup vs baseline: 1.0097x; 1.0097x over previous
#include <cuda_runtime.h>

// fullConv4d: x[2][16][24][24][24][24] (*) w[16][16][3][3][3][3] + b, SAME pad.
// R2: packed-fp32 FFMA2 (fma.rn.f32x2) with co-pair accumulators; weight pairs
// come straight out of smem via ld.shared.v2.b64 (broadcast), x scalars are
// duplicated with mov.b64 on the alu pipe. 2x fp32 flop/instr on the fma pipe.

#define S      24
#define NCI    16
#define NCO    16
#define TILE   4
#define HALO   6
#define NT     (S / TILE)
#define HALO4  (HALO*HALO*HALO*HALO)   // 1296

#define ST_T 1
#define ST_D 24
#define ST_W 576
#define ST_H 13824
#define ST_C 331776
#define ST_B (16 * 331776)

#define WS_FLOATS (NCI * 81 * NCO)     // 20736
#define XS_FLOATS (NCI * HALO4)        // 20736
#define SMEM_BYTES ((WS_FLOATS + XS_FLOATS) * (int)sizeof(float))  // 165888

typedef unsigned long long u64t;

__device__ __forceinline__ u64t ffma2(u64t a, u64t b, u64t c) {
    u64t d;
    asm("fma.rn.f32x2 %0, %1, %2, %3;" : "=l"(d) : "l"(a), "l"(b), "l"(c));
    return d;
}

__device__ __forceinline__ u64t dup2(float f) {
    u64t d;
    asm("mov.b64 %0, {%1, %1};" : "=l"(d) : "f"(f));
    return d;
}

__device__ __forceinline__ void unpack2(u64t v, float& lo, float& hi) {
    asm("mov.b64 {%0, %1}, %2;" : "=f"(lo), "=f"(hi) : "l"(v));
}

// 16B-aligned shared load of two packed-f32x2 weight pairs.
__device__ __forceinline__ void lds_wpair(const float* p, u64t& a, u64t& b) {
    asm("ld.shared.v2.b64 {%0, %1}, [%2];"
        : "=l"(a), "=l"(b)
        : "l"(__cvta_generic_to_shared(p)));
}

__global__ __launch_bounds__(256, 1)
void conv4d_ffma2_kernel(const float* __restrict__ x,
                         const float* __restrict__ wgt,
                         const float* __restrict__ bias,
                         float* __restrict__ out) {
    extern __shared__ float smem[];
    float* ws = smem;               // [ci][tap(81)][co]  (co contiguous)
    float* xs = smem + WS_FLOATS;   // [ci][6][6][6][6]

    const int tid = threadIdx.x;

    // ---- Stage weights transposed: wgt[co][ci*81+tap] -> ws[(ci*81+tap)*16+co]
    for (int i = tid; i < NCO * NCI * 81; i += 256) {
        int co = i / (NCI * 81);
        int r  = i - co * (NCI * 81);
        ws[r * 16 + co] = wgt[i];
    }

    // ---- Block -> (b, tile origin)
    int bid = blockIdx.x;
    const int tT = bid % NT; bid /= NT;
    const int tD = bid % NT; bid /= NT;
    const int tW = bid % NT; bid /= NT;
    const int tH = bid % NT; bid /= NT;
    const int b  = bid;

    const int oh0 = tH * TILE, ow0 = tW * TILE, od0 = tD * TILE, ot0 = tT * TILE;

    // ---- Halo'd input tile (zero padded)
    const float* xb = x + (size_t)b * ST_B;
    for (int i = tid; i < NCI * HALO4; i += 256) {
        int it = i % HALO; int r = i / HALO;
        int id = r % HALO; r /= HALO;
        int iw = r % HALO; r /= HALO;
        int ih = r % HALO; int ci = r / HALO;
        int gh = oh0 + ih - 1, gw = ow0 + iw - 1;
        int gd = od0 + id - 1, gt = ot0 + it - 1;
        float v = 0.0f;
        if ((unsigned)gh < (unsigned)S && (unsigned)gw < (unsigned)S &&
            (unsigned)gd < (unsigned)S && (unsigned)gt < (unsigned)S)
            v = xb[ci * ST_C + gh * ST_H + gw * ST_W + gd * ST_D + gt];
        xs[i] = v;
    }
    __syncthreads();

    // ---- Thread -> (co-group of 4, position h,w,d; 4 t positions)
    const int co4 = tid >> 6;        // 0..3 (uniform per warp -> w loads broadcast)
    const int p   = tid & 63;
    const int dd  = p & 3;
    const int w4  = (p >> 2) & 3;
    const int hh  = p >> 4;

    // acc pairs: [co-pair 0 = (4co4+0,4co4+1), 1 = (4co4+2,4co4+3)][t]
    u64t acc01[4], acc23[4];
    #pragma unroll
    for (int t = 0; t < 4; ++t) { acc01[t] = 0ull; acc23[t] = 0ull; }

    for (int ci = 0; ci < NCI; ++ci) {
        const float* xci = xs + ci * HALO4;
        const float* wci = ws + ci * (81 * 16) + co4 * 4;
        #pragma unroll 1
        for (int kh = 0; kh < 3; ++kh) {
            #pragma unroll 1
            for (int kw = 0; kw < 3; ++kw) {
                // 18 consecutive floats cover kd=0..2 rows (each 6 wide).
                const float* xr = xci + (hh + kh) * 216 + (w4 + kw) * 36 + dd * 6;
                float xv[18];
                #pragma unroll
                for (int j = 0; j < 9; ++j) {
                    float2 v = *reinterpret_cast<const float2*>(xr + 2 * j);
                    xv[2 * j]     = v.x;
                    xv[2 * j + 1] = v.y;
                }
                const float* wrow = wci + ((kh * 3 + kw) * 9) * 16;
                #pragma unroll
                for (int kd = 0; kd < 3; ++kd) {
                    u64t xd[6];
                    #pragma unroll
                    for (int m = 0; m < 6; ++m) xd[m] = dup2(xv[6 * kd + m]);
                    #pragma unroll
                    for (int kt = 0; kt < 3; ++kt) {
                        u64t w01, w23;
                        lds_wpair(wrow + (kd * 3 + kt) * 16, w01, w23);
                        #pragma unroll
                        for (int t = 0; t < 4; ++t) {
                            acc01[t] = ffma2(w01, xd[t + kt], acc01[t]);
                            acc23[t] = ffma2(w23, xd[t + kt], acc23[t]);
                        }
                    }
                }
            }
        }
    }

    // ---- Epilogue: unpack, add bias, vectorized store (t-run 16B aligned)
    float* ob = out + (size_t)b * ST_B + (oh0 + hh) * ST_H + (ow0 + w4) * ST_W
                + (od0 + dd) * ST_D + ot0;
    const float b0 = bias[co4 * 4 + 0];
    const float b1 = bias[co4 * 4 + 1];
    const float b2 = bias[co4 * 4 + 2];
    const float b3 = bias[co4 * 4 + 3];

    float4 r0, r1, r2, r3;
    float lo, hi;
    unpack2(acc01[0], lo, hi); r0.x = lo + b0; r1.x = hi + b1;
    unpack2(acc01[1], lo, hi); r0.y = lo + b0; r1.y = hi + b1;
    unpack2(acc01[2], lo, hi); r0.z = lo + b0; r1.z = hi + b1;
    unpack2(acc01[3], lo, hi); r0.w = lo + b0; r1.w = hi + b1;
    unpack2(acc23[0], lo, hi); r2.x = lo + b2; r3.x = hi + b3;
    unpack2(acc23[1], lo, hi); r2.y = lo + b2; r3.y = hi + b3;
    unpack2(acc23[2], lo, hi); r2.z = lo + b2; r3.z = hi + b3;
    unpack2(acc23[3], lo, hi); r2.w = lo + b2; r3.w = hi + b3;

    *reinterpret_cast<float4*>(ob + (co4 * 4 + 0) * ST_C) = r0;
    *reinterpret_cast<float4*>(ob + (co4 * 4 + 1) * ST_C) = r1;
    *reinterpret_cast<float4*>(ob + (co4 * 4 + 2) * ST_C) = r2;
    *reinterpret_cast<float4*>(ob + (co4 * 4 + 3) * ST_C) = r3;
}

extern "C" void kernel_launch(void* const* d_in, const int* in_sizes, int n_in,
                              void* d_out, int out_size) {
    const float* x   = (const float*)d_in[0];
    const float* w   = (const float*)d_in[1];
    const float* bia = (const float*)d_in[2];
    float* out       = (float*)d_out;

    cudaFuncSetAttribute(conv4d_ffma2_kernel,
                         cudaFuncAttributeMaxDynamicSharedMemorySize, SMEM_BYTES);

    const int grid = 2 * NT * NT * NT * NT;  // 2592
    conv4d_ffma2_kernel<<<grid, 256, SMEM_BYTES>>>(x, w, bia, out);
}

// round 4
// speedup vs baseline: 1.7803x; 1.7632x over previous
#include <cuda_runtime.h>
#include <cstdint>

// fullConv4d via tf32 mma.sync (m16n8k8) implicit GEMM.  M=co16, N=spatial(d,t), K=(tap,ci).
// CTA: (b, h, w, d-tile 8) x t24 x co16.  8 warps: warp = 1 d-row, 3 n8 t-tiles.
// smem slab [d'10][t'26][ci16 interleaved], 64B rows, chunk-XOR swizzle by (row>>1)&3.
// Weights staged once: ws[tap81][co16][ci16], tap stride 276 floats.

#define ST_T 1
#define ST_D 24
#define ST_W 576
#define ST_H 13824
#define ST_C 331776

#define WS_STRIDE 276                    // floats per tap block (16*16=256 + pad)
#define WS_FLOATS (81 * WS_STRIDE)       // 22356
#define SLAB_FLOATS (10 * 26 * 16)       // 4160
#define SMEM_BYTES ((WS_FLOATS + SLAB_FLOATS) * 4)   // 106064

static __device__ __forceinline__ float rnd_tf32(float f) {
    uint32_t u;
    asm("cvt.rna.tf32.f32 %0, %1;" : "=r"(u) : "f"(f));
    return __uint_as_float(u);
}

static __device__ __forceinline__ void mma_step(float* d,
                                                float a0, float a1, float a2, float a3,
                                                float b0, float b1) {
    asm volatile(
        "mma.sync.aligned.m16n8k8.row.col.f32.tf32.tf32.f32 "
        "{%0,%1,%2,%3}, {%4,%5,%6,%7}, {%8,%9}, {%0,%1,%2,%3};"
        : "+f"(d[0]), "+f"(d[1]), "+f"(d[2]), "+f"(d[3])
        : "r"(__float_as_uint(a0)), "r"(__float_as_uint(a1)),
          "r"(__float_as_uint(a2)), "r"(__float_as_uint(a3)),
          "r"(__float_as_uint(b0)), "r"(__float_as_uint(b1)));
}

__global__ __launch_bounds__(256, 2)
void conv4d_hmma_kernel(const float* __restrict__ x,
                        const float* __restrict__ wgt,
                        const float* __restrict__ bias,
                        float* __restrict__ out) {
    extern __shared__ float sm[];
    float* ws   = sm;                 // [tap][co16][ci16 swizzled], stride 276
    float* slab = sm + WS_FLOATS;     // [d'10][t'26][ci16 swizzled]

    const int tid = threadIdx.x;
    const int wid = tid >> 5;
    const int l   = tid & 31;
    const int r   = l >> 2;                    // groupID: A row (co), B col (n)
    const int cA  = (l & 3) ^ ((r >> 1) & 3);  // swizzled chunk for A (key of rows r and r+8 equal)

    // ---- decode block ----
    int bi = blockIdx.x;
    const int dt = bi % 3;  bi /= 3;
    const int w  = bi % 24; bi /= 24;
    const int h  = bi % 24; bi /= 24;
    const int b  = bi;
    const int d0 = dt * 8;
    const float* xb = x + (size_t)b * 16 * ST_C;

    // ---- stage weights once: coalesced (tap-fastest octets), conflict-free STS ----
    for (int i = tid; i < 11 * 16 * 4 * 32; i += 256) {
        const int lane5 = i & 31;
        const int tl = lane5 >> 2, j = lane5 & 3;
        int rest = i >> 5;
        const int co = rest & 15; rest >>= 4;
        const int c  = rest & 3;
        const int t8 = rest >> 2;
        const int tap = t8 * 8 + tl;
        if (tap < 81) {
            const int ci = c + 4 * j;
            const float v = rnd_tf32(__ldg(&wgt[(co * 16 + ci) * 81 + tap]));
            ws[tap * WS_STRIDE + co * 16 + ((c ^ ((co >> 1) & 3)) << 2) + j] = v;
        }
    }

    float acc[3][4];
    #pragma unroll
    for (int j = 0; j < 3; ++j)
        #pragma unroll
        for (int q = 0; q < 4; ++q) acc[j][q] = 0.0f;

    for (int khw = 0; khw < 9; ++khw) {
        const int kh = khw / 3, kw = khw - 3 * (khw / 3);
        const int gh = h + kh - 1, gw = w + kw - 1;
        const bool live = ((unsigned)gh < 24u) && ((unsigned)gw < 24u);

        __syncthreads();   // previous stage's fragment reads done (also orders ws on khw=0)
        if (live) {
            // stage slab: item = (chunk c, point pt); 4 gmem floats -> 1 STS.128
            for (int i = tid; i < 1040; i += 256) {
                const int c  = i & 3;
                const int pt = i >> 2;
                const int dl = pt / 26;
                const int tp = pt - dl * 26;
                const int gd = d0 + dl - 1;
                const int gt = tp - 1;
                float4 v = make_float4(0.f, 0.f, 0.f, 0.f);
                if ((unsigned)gd < 24u && (unsigned)gt < 24u) {
                    const float* p = xb + (size_t)c * ST_C + gh * ST_H + gw * ST_W
                                     + gd * ST_D + gt;
                    v.x = rnd_tf32(p[0]);
                    v.y = rnd_tf32(p[4 * ST_C]);
                    v.z = rnd_tf32(p[8 * ST_C]);
                    v.w = rnd_tf32(p[12 * ST_C]);
                }
                *reinterpret_cast<float4*>(slab + pt * 16 + ((c ^ ((pt >> 1) & 3)) << 2)) = v;
            }
        }
        __syncthreads();
        if (!live) continue;

        #pragma unroll
        for (int kd = 0; kd < 3; ++kd) {
            #pragma unroll
            for (int kt = 0; kt < 3; ++kt) {
                const float* wt = ws + (kh * 27 + kw * 9 + kd * 3 + kt) * WS_STRIDE;
                const float4 aL = *reinterpret_cast<const float4*>(wt + r * 16 + (cA << 2));
                const float4 aH = *reinterpret_cast<const float4*>(wt + (r + 8) * 16 + (cA << 2));
                #pragma unroll
                for (int j = 0; j < 3; ++j) {
                    const int pt = (wid + kd) * 26 + j * 8 + kt + r;
                    const int cB = (l & 3) ^ ((pt >> 1) & 3);
                    const float4 bv = *reinterpret_cast<const float4*>(slab + pt * 16 + (cB << 2));
                    // k-step 0 (ci 0..7), k-step 1 (ci 8..15)
                    mma_step(acc[j], aL.x, aH.x, aL.y, aH.y, bv.x, bv.y);
                    mma_step(acc[j], aL.z, aH.z, aL.w, aH.w, bv.z, bv.w);
                }
            }
        }
    }

    // ---- epilogue: D rows = co r, r+8; cols = t within tile ----
    const float bv0 = bias[r];
    const float bv1 = bias[r + 8];
    const size_t base = (size_t)b * 16 * ST_C + (size_t)h * ST_H + (size_t)w * ST_W
                        + (size_t)(d0 + wid) * ST_D;
    #pragma unroll
    for (int j = 0; j < 3; ++j) {
        const int t = j * 8 + 2 * (l & 3);
        float2 lo = make_float2(acc[j][0] + bv0, acc[j][1] + bv0);
        float2 hi = make_float2(acc[j][2] + bv1, acc[j][3] + bv1);
        *reinterpret_cast<float2*>(out + base + (size_t)r * ST_C + t) = lo;
        *reinterpret_cast<float2*>(out + base + (size_t)(r + 8) * ST_C + t) = hi;
    }
}

extern "C" void kernel_launch(void* const* d_in, const int* in_sizes, int n_in,
                              void* d_out, int out_size) {
    const float* x   = (const float*)d_in[0];
    const float* w   = (const float*)d_in[1];
    const float* bia = (const float*)d_in[2];
    float* out       = (float*)d_out;

    cudaFuncSetAttribute(conv4d_hmma_kernel,
                         cudaFuncAttributeMaxDynamicSharedMemorySize, SMEM_BYTES);

    const int grid = 2 * 24 * 24 * 3;   // 3456
    conv4d_hmma_kernel<<<grid, 256, SMEM_BYTES>>>(x, w, bia, out);
}

// round 5
// speedup vs baseline: 3.6600x; 2.0559x over previous
#include <cuda_runtime.h>
#include <cstdint>

// fullConv4d via tf32 mma.sync m16n8k8, flipped orientation: M=spatial, N=co, K=(ci,kt).
// CTA = (b, h, w-tile 2, d-tile 8): 384 outputs x 16 co. 8 warps = (wo 0-1) x (d-pair 0-3),
// each warp: 48 spatial (2 d-rows x 24 t) = 3 m-tiles, 2 co n-tiles, accum in regs over all taps.
// Slab [w'4][d'10][t'26][ci16 interleaved {c,c+4,c+8,c+12}] -> all fragment loads are
// contiguous 512B/warp, immediate-offset LDS, no swizzle. Weights staged per kh.

#define ST_T 1
#define ST_D 24
#define ST_W 576
#define ST_H 13824
#define ST_C 331776

#define WS_STRIDE  260
#define WS_FLOATS  (27 * WS_STRIDE)          // 7020
#define SLAB_FLOATS (4 * 10 * 26 * 16)       // 16640
#define SMEM_BYTES ((WS_FLOATS + SLAB_FLOATS) * 4)   // 94640

static __device__ __forceinline__ float rnd_tf32(float f) {
    uint32_t u;
    asm("cvt.rna.tf32.f32 %0, %1;" : "=r"(u) : "f"(f));
    return __uint_as_float(u);
}

static __device__ __forceinline__ void mma_step(float* d,
                                                float a0, float a1, float a2, float a3,
                                                float b0, float b1) {
    asm volatile(
        "mma.sync.aligned.m16n8k8.row.col.f32.tf32.tf32.f32 "
        "{%0,%1,%2,%3}, {%4,%5,%6,%7}, {%8,%9}, {%0,%1,%2,%3};"
        : "+f"(d[0]), "+f"(d[1]), "+f"(d[2]), "+f"(d[3])
        : "r"(__float_as_uint(a0)), "r"(__float_as_uint(a1)),
          "r"(__float_as_uint(a2)), "r"(__float_as_uint(a3)),
          "r"(__float_as_uint(b0)), "r"(__float_as_uint(b1)));
}

__global__ __launch_bounds__(256, 2)
void conv4d_hmma2_kernel(const float* __restrict__ x,
                         const float* __restrict__ wgt,
                         const float* __restrict__ bias,
                         float* __restrict__ out) {
    extern __shared__ float sm[];
    float* ws   = sm;                 // [tap27][co16][chunk4][4]  (stride 260)
    float* slab = sm + WS_FLOATS;     // [pt 1040][16]  pt = (w'*10+d')*26 + t'

    const int tid = threadIdx.x;
    const int wid = tid >> 5;
    const int l   = tid & 31;
    const int g   = l >> 2;           // groupID
    const int c   = l & 3;            // threadID in group
    const int wo  = wid >> 2;         // warp's w-output (0/1)
    const int dp  = wid & 3;          // warp's d-pair (0..3)

    // ---- decode block ----
    int bi = blockIdx.x;
    const int dt = bi % 3;  bi /= 3;
    const int wt = bi % 12; bi /= 12;
    const int h  = bi % 24; bi /= 24;
    const int b  = bi;
    const int d0 = dt * 8;
    const int w0 = wt * 2;
    const float* xb = x + (size_t)b * 16 * ST_C;

    float acc[3][2][4];
    #pragma unroll
    for (int j = 0; j < 3; ++j)
        #pragma unroll
        for (int u = 0; u < 2; ++u)
            #pragma unroll
            for (int q = 0; q < 4; ++q) acc[j][u][q] = 0.0f;

    for (int kh = 0; kh < 3; ++kh) {
        const int gh = h + kh - 1;
        if ((unsigned)gh >= 24u) continue;     // uniform across block

        __syncthreads();   // previous compute's smem reads complete

        // ---- stage weights for this kh: lane = tap_local (kw*9+kd*3+kt) ----
        for (int row = wid; row < 256; row += 8) {
            if (l < 27) {
                const int co = row >> 4, ci = row & 15;
                const float v = rnd_tf32(__ldg(&wgt[(size_t)(co * 16 + ci) * 81 + kh * 27 + l]));
                ws[l * WS_STRIDE + co * 16 + ((ci & 3) << 2) + (ci >> 2)] = v;
            }
        }

        // ---- stage slab: 1040 points x 4 chunks, chunk fastest (contiguous STS) ----
        for (int i = tid; i < 4160; i += 256) {
            const int cc = i & 3;
            const int pt = i >> 2;
            const int t  = pt % 26;
            const int rr = pt / 26;
            const int dl = rr % 10;
            const int wl = rr / 10;
            const int gw = w0 + wl - 1, gd = d0 + dl - 1, gt = t - 1;
            float4 v = make_float4(0.f, 0.f, 0.f, 0.f);
            if ((unsigned)gw < 24u && (unsigned)gd < 24u && (unsigned)gt < 24u) {
                const float* p = xb + (size_t)cc * ST_C + gh * ST_H + gw * ST_W
                                 + gd * ST_D + gt;
                v.x = rnd_tf32(p[0]);
                v.y = rnd_tf32(p[4 * ST_C]);
                v.z = rnd_tf32(p[8 * ST_C]);
                v.w = rnd_tf32(p[12 * ST_C]);
            }
            *reinterpret_cast<float4*>(slab + pt * 16 + cc * 4) = v;
        }
        __syncthreads();

        // ---- compute: all addresses = base + lane*4 + immediate ----
        const float* pA = slab + (wo * 260 + dp * 52) * 16 + l * 4;
        const float* pW = ws + l * 4;

        #pragma unroll
        for (int tl = 0; tl < 27; ++tl) {
            const int kw = tl / 9, kd = (tl % 9) / 3, kt = tl % 3;
            const int K = (kw * 260 + kd * 26 + kt) * 16;

            const float4 wv0 = *reinterpret_cast<const float4*>(pW + tl * WS_STRIDE);
            const float4 wv1 = *reinterpret_cast<const float4*>(pW + tl * WS_STRIDE + 128);

            // m-tile (L,H) point offsets: t0:(0,8)  t1:(16,26)  t2:(34,42)
            const int offL[3] = {0, 16, 34};
            const int offH[3] = {8, 26, 42};
            #pragma unroll
            for (int j = 0; j < 3; ++j) {
                const float4 aL = *reinterpret_cast<const float4*>(pA + K + offL[j] * 16);
                const float4 aH = *reinterpret_cast<const float4*>(pA + K + offH[j] * 16);
                mma_step(acc[j][0], aL.x, aH.x, aL.y, aH.y, wv0.x, wv0.y);
                mma_step(acc[j][0], aL.z, aH.z, aL.w, aH.w, wv0.z, wv0.w);
                mma_step(acc[j][1], aL.x, aH.x, aL.y, aH.y, wv1.x, wv1.y);
                mma_step(acc[j][1], aL.z, aH.z, aL.w, aH.w, wv1.z, wv1.w);
            }
        }
    }

    // ---- epilogue: D rows = spatial (g, g+8 per tile), cols = co (2c, 2c+1 per n-tile) ----
    float* ob = out + (size_t)b * 16 * ST_C + (size_t)h * ST_H + (size_t)(w0 + wo) * ST_W;
    const int dE = d0 + 2 * dp, dO = dE + 1;
    const int dLs[3] = {dE, dE, dO};
    const int tLs[3] = {0, 16, 8};     // + g
    const int dHs[3] = {dE, dO, dO};
    const int tHs[3] = {8, 0, 16};     // + g
    #pragma unroll
    for (int u = 0; u < 2; ++u) {
        const int co0 = u * 8 + 2 * c;
        const float b0 = bias[co0];
        const float b1 = bias[co0 + 1];
        #pragma unroll
        for (int j = 0; j < 3; ++j) {
            const size_t iL = (size_t)dLs[j] * ST_D + (tLs[j] + g);
            const size_t iH = (size_t)dHs[j] * ST_D + (tHs[j] + g);
            ob[(size_t)co0 * ST_C + iL]       = acc[j][u][0] + b0;
            ob[(size_t)(co0 + 1) * ST_C + iL] = acc[j][u][1] + b1;
            ob[(size_t)co0 * ST_C + iH]       = acc[j][u][2] + b0;
            ob[(size_t)(co0 + 1) * ST_C + iH] = acc[j][u][3] + b1;
        }
    }
}

extern "C" void kernel_launch(void* const* d_in, const int* in_sizes, int n_in,
                              void* d_out, int out_size) {
    const float* x   = (const float*)d_in[0];
    const float* w   = (const float*)d_in[1];
    const float* bia = (const float*)d_in[2];
    float* out       = (float*)d_out;

    cudaFuncSetAttribute(conv4d_hmma2_kernel,
                         cudaFuncAttributeMaxDynamicSharedMemorySize, SMEM_BYTES);

    const int grid = 2 * 24 * 12 * 3;   // 1728
    conv4d_hmma2_kernel<<<grid, 256, SMEM_BYTES>>>(x, w, bia, out);
}

// round 7
// speedup vs baseline: 4.1519x; 1.1344x over previous
#include <cuda_runtime.h>
#include <cuda_fp16.h>
#include <cstdint>

// fullConv4d via fp16 mma.sync m16n8k16 (fp32 accum). M=spatial, N=co, K=(ci16 x kt).
// CTA = (b, h, w-tile 2, d-tile 8). 8 warps = (wo 0-1) x (d-pair 0-3).
// Warp m-tiles: tile j = { (dE, t=8j..8j+7), (dO, t=8j..8j+7) }; slab-local H = L + 26
// baked into the ldmatrix per-lane row map (lanes 8-15/24-31 -> +26). One LDSM.x4/tile/tap.
// Weights staged in B-fragment order: 1 LDS.128 per tap serves both co n-tiles.

#define ST_T 1
#define ST_D 24
#define ST_W 576
#define ST_H 13824
#define ST_C 331776

#define SLAB_BYTES (1040 * 32)             // 33280
#define WS_BYTES   (27 * 32 * 16)          // 13824
#define SMEM_BYTES (SLAB_BYTES + WS_BYTES) // 47104

static __device__ __forceinline__ uint32_t smem_u32(const void* p) {
    uint32_t a;
    asm("{ .reg .u64 t; cvta.to.shared.u64 t, %1; cvt.u32.u64 %0, t; }" : "=r"(a) : "l"(p));
    return a;
}

static __device__ __forceinline__ uint32_t pack2(float a, float b) {
    __half2 h = __floats2half2_rn(a, b);   // lo = a, hi = b
    return *reinterpret_cast<uint32_t*>(&h);
}

static __device__ __forceinline__ void mma16816(float* d, uint32_t a0, uint32_t a1,
                                                uint32_t a2, uint32_t a3,
                                                uint32_t b0, uint32_t b1) {
    asm volatile(
        "mma.sync.aligned.m16n8k16.row.col.f32.f16.f16.f32 "
        "{%0,%1,%2,%3}, {%4,%5,%6,%7}, {%8,%9}, {%0,%1,%2,%3};"
        : "+f"(d[0]), "+f"(d[1]), "+f"(d[2]), "+f"(d[3])
        : "r"(a0), "r"(a1), "r"(a2), "r"(a3), "r"(b0), "r"(b1));
}

__global__ __launch_bounds__(256, 2)
void conv4d_hmma16_kernel(const float* __restrict__ x,
                          const float* __restrict__ wgt,
                          const float* __restrict__ bias,
                          float* __restrict__ out) {
    extern __shared__ char smc[];
    const uint32_t slabAddr = smem_u32(smc);
    const uint32_t wsAddr   = slabAddr + SLAB_BYTES;

    const int tid = threadIdx.x;
    const int wid = tid >> 5;
    const int l   = tid & 31;
    const int g   = l >> 2;
    const int c   = l & 3;
    const int wo  = wid >> 2;
    const int dp  = wid & 3;

    // ---- decode block ----
    int bi = blockIdx.x;
    const int dt = bi % 3;  bi /= 3;
    const int wt = bi % 12; bi /= 12;
    const int h  = bi % 24; bi /= 24;
    const int b  = bi;
    const int d0 = dt * 8;
    const int w0 = wt * 2;
    const float* xb = x + (size_t)b * 16 * ST_C;

    // ldmatrix per-lane address: matrices 0/2 (lanes 0-7,16-23) = L rows (d' = 2dp),
    // matrices 1/3 (lanes 8-15,24-31) = H rows (d' = 2dp+1 -> +26 slab rows).
    const int rowmap = (l & 8) ? (26 + (l & 7)) : (l & 7);
    const uint32_t aLane = slabAddr + (uint32_t)((wo * 260 + dp * 52 + rowmap) * 32
                                                 + (l >> 4) * 16);

    // ---- precompute slab-staging slots (kh-invariant) ----
    int      gOff[9];
    uint32_t sAdr[9];
    uint32_t vmask = 0;
    #pragma unroll
    for (int k = 0; k < 9; ++k) {
        const int i = tid + k * 256;
        gOff[k] = 0; sAdr[k] = 0;
        if (i < 2080) {
            const int o  = i & 1;
            const int pt = i >> 1;
            const int t  = pt % 26;
            const int rr = pt / 26;
            const int dl = rr % 10;
            const int wl = rr / 10;
            const int gw = w0 + wl - 1, gd = d0 + dl - 1, gt = t - 1;
            sAdr[k] = slabAddr + (uint32_t)(pt * 32 + o * 16);
            vmask |= (1u << k);
            if ((unsigned)gw < 24u && (unsigned)gd < 24u && (unsigned)gt < 24u) {
                gOff[k] = o * 8 * ST_C + gw * ST_W + gd * ST_D + gt;
                vmask |= (1u << (k + 16));
            }
        }
    }

    float acc[3][2][4];
    #pragma unroll
    for (int j = 0; j < 3; ++j)
        #pragma unroll
        for (int u = 0; u < 2; ++u)
            #pragma unroll
            for (int q = 0; q < 4; ++q) acc[j][u][q] = 0.0f;

    for (int kh = 0; kh < 3; ++kh) {
        const int gh = h + kh - 1;
        if ((unsigned)gh >= 24u) continue;            // uniform across block

        __syncthreads();   // previous iteration's smem reads complete

        // ---- stage weights in B-fragment order: [tap][lane][b0,b1,b0',b1'] ----
        for (int i = tid; i < 864; i += 256) {
            const int tl = i >> 5, l5 = i & 31;
            const int gg = l5 >> 2, cc = (l5 & 3) << 1;
            const float* wp = wgt + kh * 27 + tl;
            #define WG(co, ci) wp[((co) * 16 + (ci)) * 81]
            const uint32_t r0 = pack2(WG(gg, cc),         WG(gg, cc + 1));
            const uint32_t r1 = pack2(WG(gg, cc + 8),     WG(gg, cc + 9));
            const uint32_t r2 = pack2(WG(gg + 8, cc),     WG(gg + 8, cc + 1));
            const uint32_t r3 = pack2(WG(gg + 8, cc + 8), WG(gg + 8, cc + 9));
            #undef WG
            asm volatile("st.shared.v4.b32 [%0], {%1,%2,%3,%4};"
                         :: "r"(wsAddr + (uint32_t)(tl * 512 + l5 * 16)),
                            "r"(r0), "r"(r1), "r"(r2), "r"(r3));
        }

        // ---- stage slab (halo'd x plane, fp16) ----
        const float* xh = xb + gh * ST_H;
        #pragma unroll
        for (int k = 0; k < 9; ++k) {
            if (vmask & (1u << k)) {
                uint32_t v0 = 0, v1 = 0, v2 = 0, v3 = 0;
                if (vmask & (1u << (k + 16))) {
                    const float* p = xh + gOff[k];
                    v0 = pack2(p[0],          p[ST_C]);
                    v1 = pack2(p[2 * ST_C],   p[3 * ST_C]);
                    v2 = pack2(p[4 * ST_C],   p[5 * ST_C]);
                    v3 = pack2(p[6 * ST_C],   p[7 * ST_C]);
                }
                asm volatile("st.shared.v4.b32 [%0], {%1,%2,%3,%4};"
                             :: "r"(sAdr[k]), "r"(v0), "r"(v1), "r"(v2), "r"(v3));
            }
        }
        __syncthreads();

        // ---- compute: 27 taps x (1 LDS.128 + 3 LDSM.x4 + 6 HMMA) ----
        const uint32_t wLane = wsAddr + (uint32_t)(l * 16);
        #pragma unroll
        for (int tl = 0; tl < 27; ++tl) {
            const int kd = (tl / 3) % 3, kt = tl % 3;
            uint32_t b0, b1, b2, b3;
            asm volatile("ld.shared.v4.b32 {%0,%1,%2,%3}, [%4];"
                         : "=r"(b0), "=r"(b1), "=r"(b2), "=r"(b3)
                         : "r"(wLane + (uint32_t)(tl * 512)));
            #pragma unroll
            for (int j = 0; j < 3; ++j) {
                const int kwb = (tl / 9) * 260;
                const uint32_t P = (uint32_t)((kwb + kd * 26 + kt + 8 * j) * 32);
                uint32_t a0, a1, a2, a3;
                asm volatile("ldmatrix.sync.aligned.m8n8.x4.shared.b16 {%0,%1,%2,%3}, [%4];"
                             : "=r"(a0), "=r"(a1), "=r"(a2), "=r"(a3)
                             : "r"(aLane + P));
                mma16816(acc[j][0], a0, a1, a2, a3, b0, b1);
                mma16816(acc[j][1], a0, a1, a2, a3, b2, b3);
            }
        }
    }

    // ---- epilogue: tile j -> L=(dE, t=8j+g) rows d0/d1, H=(dO, t=8j+g) rows d2/d3 ----
    float* ob = out + (size_t)b * 16 * ST_C + (size_t)h * ST_H + (size_t)(w0 + wo) * ST_W;
    const int dE = d0 + 2 * dp, dO = dE + 1;
    #pragma unroll
    for (int u = 0; u < 2; ++u) {
        const int co0 = u * 8 + 2 * c;
        const float b0v = bias[co0];
        const float b1v = bias[co0 + 1];
        #pragma unroll
        for (int j = 0; j < 3; ++j) {
            const int t = 8 * j + g;
            ob[(size_t)co0 * ST_C + (size_t)dE * ST_D + t]       = acc[j][u][0] + b0v;
            ob[(size_t)(co0 + 1) * ST_C + (size_t)dE * ST_D + t] = acc[j][u][1] + b1v;
            ob[(size_t)co0 * ST_C + (size_t)dO * ST_D + t]       = acc[j][u][2] + b0v;
            ob[(size_t)(co0 + 1) * ST_C + (size_t)dO * ST_D + t] = acc[j][u][3] + b1v;
        }
    }
}

extern "C" void kernel_launch(void* const* d_in, const int* in_sizes, int n_in,
                              void* d_out, int out_size) {
    const float* x   = (const float*)d_in[0];
    const float* w   = (const float*)d_in[1];
    const float* bia = (const float*)d_in[2];
    float* out       = (float*)d_out;

    cudaFuncSetAttribute(conv4d_hmma16_kernel,
                         cudaFuncAttributeMaxDynamicSharedMemorySize, SMEM_BYTES);

    const int grid = 2 * 24 * 12 * 3;   // 1728
    conv4d_hmma16_kernel<<<grid, 256, SMEM_BYTES>>>(x, w, bia, out);
}